// round 3
// baseline (speedup 1.0000x reference)
#include <cuda_runtime.h>
#include <cuda_bf16.h>
#include <cstdint>

#define BB 32
#define TT 168
#define SS 32      // N_HYDRO stations
#define NM 64      // meteo nodes
#define NN 96      // total nodes
#define EE 384     // edges
#define HG 64      // HID_GNN
#define HH 128     // HID_LSTM
#define G4 512     // 4*HH gates
#define FUT 24
#define GG (BB*TT) // 5376 graphs

// ---------------- device scratch (allocation-free rule: __device__ globals) ----
__device__ float4 g_Whh4[SS*32*G4];                 // [s][k4][j], pairs-of-pairs of Whh[s][j][k]
__device__ float  g_WihT[SS*HG*G4];                 // [s][k][j]
__device__ float  g_bsum[SS*G4];                    // bih + bhh
__device__ float  g_feat[(size_t)SS*GG*HG];         // [s][g][k]
__device__ float  g_Gin [(size_t)SS*GG*G4];         // [s][g][j]  input-gate preactivations (+bias)

// ---------------- packed fp32x2 helpers (sm_100+) ------------------------------
__device__ __forceinline__ void ffma2(unsigned long long &d, unsigned long long a, unsigned long long b) {
    asm("fma.rn.f32x2 %0, %1, %2, %0;" : "+l"(d) : "l"(a), "l"(b));
}
__device__ __forceinline__ float2 unpack2(unsigned long long v) {
    float2 r; asm("mov.b64 {%0,%1}, %2;" : "=f"(r.x), "=f"(r.y) : "l"(v)); return r;
}
__device__ __forceinline__ unsigned long long pack2(float x, float y) {
    unsigned long long r; asm("mov.b64 %0, {%1,%2};" : "=l"(r) : "f"(x), "f"(y)); return r;
}
__device__ __forceinline__ float lrelu(float v) { return v > 0.f ? v : 0.01f*v; }
__device__ __forceinline__ float sigmoidf_(float x) { return 1.f/(1.f + __expf(-x)); }

// ================== K0: weight repack =========================================
__global__ void k0_prep(const float* __restrict__ Wih, const float* __restrict__ Whh,
                        const float* __restrict__ bih, const float* __restrict__ bhh) {
    int i = blockIdx.x*blockDim.x + threadIdx.x;
    if (i < SS*32*G4) {
        int s = i / (32*G4); int r = i % (32*G4); int k4 = r / G4; int j = r % G4;
        const float* w = Whh + (size_t)(s*G4 + j)*HH + k4*4;
        g_Whh4[i] = make_float4(w[0], w[1], w[2], w[3]);
    }
    if (i < SS*HG*G4) {
        int s = i / (HG*G4); int r = i % (HG*G4); int k = r / G4; int j = r % G4;
        g_WihT[i] = Wih[(size_t)(s*G4 + j)*HG + k];
    }
    if (i < SS*G4) g_bsum[i] = bih[i] + bhh[i];
}

// ================== K1: GNN scalars -> 64-d hydro features ====================
// edge_index may be int32 (JAX default, x64 disabled) or int64. Read only as
// int32 (safe for both: int64 buffer is larger). Detect layout: little-endian
// int64 values in [0,96) have all odd int32 words == 0; a genuine int32 edge
// list has ~zero probability of 383 odd words all being zero.
__global__ void k1_feat(const float* __restrict__ hydro, const float* __restrict__ meteo,
                        const int* __restrict__ edges32,
                        const float* __restrict__ Wroot, const float* __restrict__ Wrel,
                        const float* __restrict__ bgnn) {
    __shared__ float xs[NN];
    __shared__ float agg[SS];
    __shared__ int   is64;
    int g = blockIdx.x;             // g = b*TT + t
    int tid = threadIdx.x;
    if (tid == 0) is64 = 1;
    if (tid < NN) xs[tid] = (tid < SS) ? hydro[(size_t)g*SS + tid]
                                       : meteo[(size_t)g*NM + (tid - SS)];
    if (tid < SS) agg[tid] = 0.f;
    __syncthreads();
    // dtype scan: reads within bounds for BOTH layouts (768 int32 = min size)
    for (int e = tid; e < 2*EE; e += blockDim.x) {
        if ((e & 1) && edges32[e] != 0) atomicExch(&is64, 0);
    }
    __syncthreads();
    const int stride = is64 ? 2 : 1;
    const int dstOff = is64 ? 2*EE : EE;
    for (int e = tid; e < EE; e += blockDim.x) {
        int dst = edges32[dstOff + e*stride];
        if (dst >= 0 && dst < SS) {             // only hydro aggregates are used
            int src = edges32[e*stride];
            if (src >= 0 && src < NN) atomicAdd(&agg[dst], xs[src]);
        }
    }
    __syncthreads();
    for (int i = tid; i < SS*HG; i += blockDim.x) {
        int s = i >> 6; int k = i & 63;
        float v = xs[s]*Wroot[k] + agg[s]*Wrel[k] + bgnn[k];
        g_feat[((size_t)s*GG + g)*HG + k] = lrelu(v);
    }
}

// ================== K2: input GEMM  Gin = feat @ WihT + bsum ==================
// per station: [5376 x 64] @ [64 x 512]; tile 64(g) x 128(j), 256 threads, f32x2
__global__ __launch_bounds__(256) void k2_gemm() {
    extern __shared__ float sm2[];
    float* As = sm2;                 // [64][66] padded
    float* Bs = sm2 + 64*66;         // [64][128]
    int s = blockIdx.z, g0 = blockIdx.x*64, j0 = blockIdx.y*128;
    int tid = threadIdx.x;

    const float4* fa = (const float4*)(g_feat + ((size_t)s*GG + g0)*HG);
    for (int i = tid; i < 64*16; i += 256) {       // A tile: 1024 float4
        int r = i >> 4, k4 = i & 15;
        float4 v = fa[r*16 + k4];
        float* d = As + r*66 + k4*4;
        d[0]=v.x; d[1]=v.y; d[2]=v.z; d[3]=v.w;
    }
    for (int i = tid; i < 64*32; i += 256) {       // B tile: 2048 float4
        int k = i >> 5, q = i & 31;
        float4 v = *(const float4*)(g_WihT + ((size_t)(s*HG + k))*G4 + j0 + q*4);
        *(float4*)(Bs + k*128 + q*4) = v;
    }
    __syncthreads();

    int ty = tid >> 4, tx = tid & 15;              // 16x16 threads, tile 4g x 8j each
    unsigned long long acc[4][4];
    #pragma unroll
    for (int i = 0; i < 4; i++)
        #pragma unroll
        for (int q = 0; q < 4; q++) acc[i][q] = 0ull;

    #pragma unroll 8
    for (int k = 0; k < 64; k++) {
        const unsigned long long* bp = (const unsigned long long*)(Bs + k*128 + tx*8);
        unsigned long long b0 = bp[0], b1 = bp[1], b2 = bp[2], b3 = bp[3];
        #pragma unroll
        for (int i = 0; i < 4; i++) {
            float a = As[(ty*4 + i)*66 + k];
            unsigned long long a2 = pack2(a, a);
            ffma2(acc[i][0], a2, b0);
            ffma2(acc[i][1], a2, b1);
            ffma2(acc[i][2], a2, b2);
            ffma2(acc[i][3], a2, b3);
        }
    }
    const float* bs = g_bsum + s*G4 + j0 + tx*8;
    #pragma unroll
    for (int i = 0; i < 4; i++) {
        int g = g0 + ty*4 + i;
        float* orow = g_Gin + ((size_t)s*GG + g)*G4 + j0 + tx*8;
        #pragma unroll
        for (int q = 0; q < 4; q++) {
            float2 v = unpack2(acc[i][q]);
            float2 o; o.x = v.x + bs[2*q]; o.y = v.y + bs[2*q+1];
            *(float2*)(orow + 2*q) = o;
        }
    }
}

// ================== K3: recurrent LSTM + head =================================
// 128 blocks = (station s, batch group of 8). 256 threads: thread owns gate rows
// j0=tid, j1=tid+256. Whh rows j<384 live in smem (192KB); rows 384..511 stream
// from L2 (hot 2MB slice). h[8][128], gate activations [8][512] in smem; c in regs.
__global__ __launch_bounds__(256, 1) void k3_lstm(const float* __restrict__ Wlin,
                                                  const float* __restrict__ blin,
                                                  float* __restrict__ out) {
    extern __shared__ char sm3[];
    float4* wsm4 = (float4*)sm3;                      // [32][384] : 196608 B
    float*  h_sm = (float*)(sm3 + 196608);            // [8][128]  : 4096 B
    float*  gact = (float*)(sm3 + 196608 + 4096);     // [8][512]  : 16384 B

    int tid = threadIdx.x;
    int s  = blockIdx.x >> 2;
    int b0 = (blockIdx.x & 3) * 8;

    const float4* gw = g_Whh4 + (size_t)s*32*G4;
    for (int i = tid; i < 32*384; i += 256) {
        int k4 = i / 384, j = i % 384;
        wsm4[i] = gw[k4*G4 + j];
    }
    for (int i = tid; i < 8*HH; i += 256) h_sm[i] = 0.f;
    __syncthreads();

    const int j0 = tid, j1 = tid + 256;
    const bool j1g = (tid >= 128);                    // j1 >= 384 -> global path
    const ulonglong2* w0p = (const ulonglong2*)wsm4 + j0;
    const ulonglong2* w1p = j1g ? ((const ulonglong2*)gw + j1)
                                : ((const ulonglong2*)wsm4 + j1);
    const int w1stride = j1g ? G4 : 384;

    // cell state registers: (b in {b2, b2+4}) x (m in {m0, m0+64})
    const int m0 = tid & 63;
    const int b2 = tid >> 6;
    float c00 = 0.f, c01 = 0.f, c10 = 0.f, c11 = 0.f;

    const float* ginbase = g_Gin + ((size_t)s*GG + (size_t)b0*TT)*G4;

    for (int t = 0; t < TT; t++) {
        // issue Gin loads first; consumed after the k-loop (DRAM latency hidden)
        float gin0[8], gin1[8];
        #pragma unroll
        for (int bi = 0; bi < 8; bi++) {
            const float* p = ginbase + (size_t)(bi*TT + t)*G4;
            gin0[bi] = p[j0];
            gin1[bi] = p[j1];
        }
        unsigned long long a0[8], a1[8];
        #pragma unroll
        for (int bi = 0; bi < 8; bi++) { a0[bi] = 0ull; a1[bi] = 0ull; }

        const ulonglong2* hp = (const ulonglong2*)h_sm;   // [8][32]
        #pragma unroll 8
        for (int k4 = 0; k4 < 32; k4++) {
            ulonglong2 w0 = w0p[k4*384];
            ulonglong2 w1 = w1p[k4*w1stride];
            #pragma unroll
            for (int bi = 0; bi < 8; bi++) {
                ulonglong2 h4 = hp[bi*32 + k4];
                ffma2(a0[bi], w0.x, h4.x);
                ffma2(a0[bi], w0.y, h4.y);
                ffma2(a1[bi], w1.x, h4.x);
                ffma2(a1[bi], w1.y, h4.y);
            }
        }
        #pragma unroll
        for (int bi = 0; bi < 8; bi++) {
            float2 v0 = unpack2(a0[bi]);
            float p0 = v0.x + v0.y + gin0[bi];            // j0 < 256 : i or f -> sigmoid
            gact[bi*G4 + j0] = sigmoidf_(p0);
            float2 v1 = unpack2(a1[bi]);
            float p1 = v1.x + v1.y + gin1[bi];            // j1<384: g->tanh, else o->sigmoid
            gact[bi*G4 + j1] = j1g ? sigmoidf_(p1) : tanhf(p1);
        }
        __syncthreads();
        // state update (i,f,g,o torch order)
        #pragma unroll
        for (int u = 0; u < 2; u++) {
            int b = b2 + 4*u;
            #pragma unroll
            for (int v = 0; v < 2; v++) {
                int m = m0 + 64*v;
                float ig = gact[b*G4 + m];
                float fg = gact[b*G4 + 128 + m];
                float gg = gact[b*G4 + 256 + m];
                float og = gact[b*G4 + 384 + m];
                float c = (u==0 ? (v==0?c00:c01) : (v==0?c10:c11));
                c = fg*c + ig*gg;
                if (u==0) { if (v==0) c00 = c; else c01 = c; }
                else      { if (v==0) c10 = c; else c11 = c; }
                h_sm[b*HH + m] = og * tanhf(c);
            }
        }
        __syncthreads();
    }

    // head: pred[b][s][f] = lrelu(h . Wlin[f] + blin[f])
    for (int i = tid; i < 8*FUT; i += 256) {
        int bi = i / FUT, f = i % FUT;
        const float* hr = h_sm + bi*HH;
        const float* wr = Wlin + f*HH;
        float acc = 0.f;
        #pragma unroll 8
        for (int m = 0; m < HH; m++) acc += hr[m]*wr[m];
        acc += blin[f];
        out[((size_t)(b0 + bi)*SS + s)*FUT + f] = lrelu(acc);
    }
}

// ================== launch =====================================================
extern "C" void kernel_launch(void* const* d_in, const int* in_sizes, int n_in,
                              void* d_out, int out_size) {
    const float* meteo = (const float*)d_in[0];
    const float* hydro = (const float*)d_in[1];
    const int*   edges = (const int*)d_in[2];     // int32 view; layout detected on device
    const float* Wroot = (const float*)d_in[3];
    const float* Wrel  = (const float*)d_in[4];
    const float* bgnn  = (const float*)d_in[5];
    const float* Wih   = (const float*)d_in[6];
    const float* Whh   = (const float*)d_in[7];
    const float* bih   = (const float*)d_in[8];
    const float* bhh   = (const float*)d_in[9];
    const float* Wlin  = (const float*)d_in[10];
    const float* blin  = (const float*)d_in[11];
    float* out = (float*)d_out;

    static_assert(GG == 84*64, "g tiling");

    const int smem2 = (64*66 + 64*128) * (int)sizeof(float);      // 49664
    const int smem3 = 196608 + 4096 + 16384;                      // 217088
    cudaFuncSetAttribute(k2_gemm, cudaFuncAttributeMaxDynamicSharedMemorySize, smem2);
    cudaFuncSetAttribute(k3_lstm, cudaFuncAttributeMaxDynamicSharedMemorySize, smem3);

    k0_prep<<<(SS*HG*G4 + 255)/256, 256>>>(Wih, Whh, bih, bhh);
    k1_feat<<<GG, 256>>>(hydro, meteo, edges, Wroot, Wrel, bgnn);
    k2_gemm<<<dim3(84, 4, SS), 256, smem2>>>();
    k3_lstm<<<SS*4, 256, smem3>>>(Wlin, blin, out);
}